// round 4
// baseline (speedup 1.0000x reference)
#include <cuda_runtime.h>
#include <cstdint>

#define SLEN  1024
#define DM    4096
#define FF    14336
#define KVDIM 1024
#define RLORA 16
#define LSCALE 2.0f

// ---------------- scratch (device globals; no allocations) ----------------
__device__ float g_h[SLEN * DM];
__device__ float g_q[SLEN * DM];
__device__ float g_k[SLEN * KVDIM];
__device__ float g_v[SLEN * KVDIM];
__device__ float g_attn[SLEN * DM];
__device__ float g_res2[SLEN * DM];
__device__ float g_gate[SLEN * FF];
__device__ float g_up[SLEN * FF];
__device__ float g_tmp[SLEN * RLORA];

// ---------------- rmsnorm: one block per row ----------------
__global__ void rmsnorm_kernel(const float* __restrict__ X, const float* __restrict__ W,
                               float* __restrict__ Y, int D)
{
    const int m = blockIdx.x, tid = threadIdx.x;   // 256 threads
    const float* x = X + (size_t)m * D;
    float s = 0.f;
    for (int k = tid * 4; k < D; k += 1024) {
        float4 v = *(const float4*)(x + k);
        s += v.x * v.x + v.y * v.y + v.z * v.z + v.w * v.w;
    }
    __shared__ float red[9];
    #pragma unroll
    for (int off = 16; off > 0; off >>= 1) s += __shfl_xor_sync(0xffffffffu, s, off);
    if ((tid & 31) == 0) red[tid >> 5] = s;
    __syncthreads();
    if (tid == 0) {
        float t = 0.f;
        #pragma unroll
        for (int i = 0; i < 8; i++) t += red[i];
        red[8] = rsqrtf(t / (float)D + 1e-5f);
    }
    __syncthreads();
    const float inv = red[8];
    float* y = Y + (size_t)m * D;
    for (int k = tid * 4; k < D; k += 1024) {
        float4 v = *(const float4*)(x + k);
        float4 w = *(const float4*)(W + k);
        v.x = v.x * inv * w.x;
        v.y = v.y * inv * w.y;
        v.z = v.z * inv * w.z;
        v.w = v.w * inv * w.w;
        *(float4*)(y + k) = v;
    }
}

// ---------------- LoRA down-projection: T[M,16] = X[M,K] @ A[16,K]^T ----------------
// grid = M blocks, 512 threads = 16 warps; warp w computes dot(X[m], A[w])
__global__ void lora_tmp_kernel(const float* __restrict__ X, const float* __restrict__ Aw,
                                float* __restrict__ T, int K)
{
    const int m = blockIdx.x;
    const int w = threadIdx.x >> 5, lane = threadIdx.x & 31;
    const float* x = X + (size_t)m * K;
    const float* a = Aw + (size_t)w * K;
    float s = 0.f;
    for (int k = lane * 4; k < K; k += 128) {
        float4 xv = *(const float4*)(x + k);
        float4 av = *(const float4*)(a + k);
        s += xv.x * av.x + xv.y * av.y + xv.z * av.z + xv.w * av.w;
    }
    #pragma unroll
    for (int off = 16; off > 0; off >>= 1) s += __shfl_xor_sync(0xffffffffu, s, off);
    if (lane == 0) T[m * RLORA + w] = s;
}

// ---------------- SGEMM NT with fused LoRA epilogue + optional residual ----------------
// C[M,N] = A[M,K] @ B[N,K]^T + LSCALE * T[M,16] @ Bl[N,16]^T (+ Res[M,N])
// BM=BN=128, BK=16, 256 threads, 8x8 microtile. M,N,K all multiples of tile sizes.
__global__ __launch_bounds__(256) void sgemm_lora(
    const float* __restrict__ A, const float* __restrict__ B,
    const float* __restrict__ T, const float* __restrict__ Bl,
    const float* __restrict__ Res, float* __restrict__ C,
    int M, int N, int K)
{
    __shared__ float As[16][128];   // As[k][m]
    __shared__ float Bs[16][128];   // Bs[k][n]
    __shared__ float Ts[128][16];   // lora T tile (row-major)
    __shared__ float BlT[16][128];  // lora B tile transposed: BlT[r][n]

    const int tid = threadIdx.x;
    const int m0 = blockIdx.y << 7, n0 = blockIdx.x << 7;

    // preload lora tiles (512 float4 total)
    #pragma unroll
    for (int it = 0; it < 2; it++) {
        const int li = it * 256 + tid;
        const int row = li >> 2, qq = li & 3;
        *(float4*)&Ts[row][qq * 4] = *(const float4*)(T + (size_t)(m0 + row) * RLORA + qq * 4);
        float4 bv = *(const float4*)(Bl + (size_t)(n0 + row) * RLORA + qq * 4);
        BlT[qq * 4 + 0][row] = bv.x;
        BlT[qq * 4 + 1][row] = bv.y;
        BlT[qq * 4 + 2][row] = bv.z;
        BlT[qq * 4 + 3][row] = bv.w;
    }

    const int ty = tid >> 4, tx = tid & 15;
    float acc[8][8];
    #pragma unroll
    for (int i = 0; i < 8; i++)
        #pragma unroll
        for (int j = 0; j < 8; j++) acc[i][j] = 0.f;

    for (int k0 = 0; k0 < K; k0 += 16) {
        __syncthreads();
        #pragma unroll
        for (int it = 0; it < 2; it++) {
            const int li = it * 256 + tid;
            const int row = li >> 2, qq = li & 3;
            float4 av = *(const float4*)(A + (size_t)(m0 + row) * K + k0 + qq * 4);
            As[qq * 4 + 0][row] = av.x;
            As[qq * 4 + 1][row] = av.y;
            As[qq * 4 + 2][row] = av.z;
            As[qq * 4 + 3][row] = av.w;
            float4 bv = *(const float4*)(B + (size_t)(n0 + row) * K + k0 + qq * 4);
            Bs[qq * 4 + 0][row] = bv.x;
            Bs[qq * 4 + 1][row] = bv.y;
            Bs[qq * 4 + 2][row] = bv.z;
            Bs[qq * 4 + 3][row] = bv.w;
        }
        __syncthreads();
        #pragma unroll
        for (int kk = 0; kk < 16; kk++) {
            float4 a0 = *(const float4*)&As[kk][ty * 8];
            float4 a1 = *(const float4*)&As[kk][ty * 8 + 4];
            float4 b0 = *(const float4*)&Bs[kk][tx * 8];
            float4 b1 = *(const float4*)&Bs[kk][tx * 8 + 4];
            const float a[8] = {a0.x, a0.y, a0.z, a0.w, a1.x, a1.y, a1.z, a1.w};
            const float b[8] = {b0.x, b0.y, b0.z, b0.w, b1.x, b1.y, b1.z, b1.w};
            #pragma unroll
            for (int i = 0; i < 8; i++)
                #pragma unroll
                for (int j = 0; j < 8; j++)
                    acc[i][j] = fmaf(a[i], b[j], acc[i][j]);
        }
    }

    // epilogue: rank-16 lora correction (+ optional residual) and store
    #pragma unroll
    for (int i = 0; i < 8; i++) {
        const int gm = m0 + ty * 8 + i;
        float tv[16];
        #pragma unroll
        for (int r4 = 0; r4 < 4; r4++) {
            float4 t4 = *(const float4*)&Ts[ty * 8 + i][r4 * 4];
            tv[r4 * 4 + 0] = t4.x; tv[r4 * 4 + 1] = t4.y;
            tv[r4 * 4 + 2] = t4.z; tv[r4 * 4 + 3] = t4.w;
        }
        float corr[8] = {0, 0, 0, 0, 0, 0, 0, 0};
        #pragma unroll
        for (int r = 0; r < 16; r++) {
            float4 c0 = *(const float4*)&BlT[r][tx * 8];
            float4 c1 = *(const float4*)&BlT[r][tx * 8 + 4];
            corr[0] = fmaf(tv[r], c0.x, corr[0]);
            corr[1] = fmaf(tv[r], c0.y, corr[1]);
            corr[2] = fmaf(tv[r], c0.z, corr[2]);
            corr[3] = fmaf(tv[r], c0.w, corr[3]);
            corr[4] = fmaf(tv[r], c1.x, corr[4]);
            corr[5] = fmaf(tv[r], c1.y, corr[5]);
            corr[6] = fmaf(tv[r], c1.z, corr[6]);
            corr[7] = fmaf(tv[r], c1.w, corr[7]);
        }
        float out[8];
        #pragma unroll
        for (int j = 0; j < 8; j++) out[j] = acc[i][j] + LSCALE * corr[j];
        const size_t base = (size_t)gm * N + n0 + tx * 8;
        if (Res) {
            float4 r0 = *(const float4*)(Res + base);
            float4 r1 = *(const float4*)(Res + base + 4);
            out[0] += r0.x; out[1] += r0.y; out[2] += r0.z; out[3] += r0.w;
            out[4] += r1.x; out[5] += r1.y; out[6] += r1.z; out[7] += r1.w;
        }
        float4 o0 = {out[0], out[1], out[2], out[3]};
        float4 o1 = {out[4], out[5], out[6], out[7]};
        *(float4*)(C + base) = o0;
        *(float4*)(C + base + 4) = o1;
    }
}

// ---------------- RoPE (interleaved pairs), in place ----------------
__global__ void rope_kernel(float* __restrict__ X, const float* __restrict__ Cc,
                            const float* __restrict__ Sn, int H, int total)
{
    const int idx = blockIdx.x * blockDim.x + threadIdx.x;
    if (idx >= total) return;
    const int i = idx & 63;
    const int rest = idx >> 6;
    const int h = rest % H;
    const int s = rest / H;
    const float c = Cc[s * 64 + i], sn = Sn[s * 64 + i];
    float* p = X + (size_t)s * (H * 128) + h * 128 + 2 * i;
    const float x1 = p[0], x2 = p[1];
    p[0] = x1 * c - x2 * sn;
    p[1] = x1 * sn + x2 * c;
}

// ---------------- flash attention fp32: 64x64 tiles, causal, GQA 4:1 ----------------
// grid = (S/64, 32 heads), 256 threads (16x16). Dynamic smem = 112 KB.
__global__ __launch_bounds__(256) void flash_kernel(
    const float* __restrict__ Q, const float* __restrict__ Kk,
    const float* __restrict__ V, float* __restrict__ O)
{
    extern __shared__ float sm[];
    float* Qs = sm;                // [128][64] transposed: Qs[k*64+r]
    float* Ks = sm + 128 * 64;     // [128][64] transposed
    float* Vs = sm + 2 * 128 * 64; // [64][128] row-major
    float* Ps = sm + 3 * 128 * 64; // [64][64]

    const int qb = blockIdx.x, head = blockIdx.y;
    const int kvh = head >> 2;
    const int tid = threadIdx.x;
    const int ty = tid >> 4, tx = tid & 15;
    const int qr0 = qb * 64;

    // load Q tile (transposed into smem)
    const float* Qg = Q + (size_t)qr0 * DM + head * 128;
    for (int li = tid; li < 2048; li += 256) {
        const int r = li >> 5, c4 = li & 31;
        float4 v = *(const float4*)(Qg + (size_t)r * DM + c4 * 4);
        Qs[(c4 * 4 + 0) * 64 + r] = v.x;
        Qs[(c4 * 4 + 1) * 64 + r] = v.y;
        Qs[(c4 * 4 + 2) * 64 + r] = v.z;
        Qs[(c4 * 4 + 3) * 64 + r] = v.w;
    }

    float m_i[4], l_i[4], acc[4][8];
    #pragma unroll
    for (int i = 0; i < 4; i++) {
        m_i[i] = -1e30f; l_i[i] = 0.f;
        #pragma unroll
        for (int j = 0; j < 8; j++) acc[i][j] = 0.f;
    }
    const float scale = 0.088388347648318447f;  // 1/sqrt(128)

    for (int kb = 0; kb <= qb; kb++) {
        __syncthreads();
        const float* Kg = Kk + (size_t)(kb * 64) * KVDIM + kvh * 128;
        const float* Vg = V + (size_t)(kb * 64) * KVDIM + kvh * 128;
        for (int li = tid; li < 2048; li += 256) {
            const int r = li >> 5, c4 = li & 31;
            float4 kv = *(const float4*)(Kg + (size_t)r * KVDIM + c4 * 4);
            Ks[(c4 * 4 + 0) * 64 + r] = kv.x;
            Ks[(c4 * 4 + 1) * 64 + r] = kv.y;
            Ks[(c4 * 4 + 2) * 64 + r] = kv.z;
            Ks[(c4 * 4 + 3) * 64 + r] = kv.w;
            float4 vv = *(const float4*)(Vg + (size_t)r * KVDIM + c4 * 4);
            *(float4*)(Vs + r * 128 + c4 * 4) = vv;
        }
        __syncthreads();

        // S = Q K^T, 4x4 per thread
        float sc[4][4];
        #pragma unroll
        for (int i = 0; i < 4; i++)
            #pragma unroll
            for (int j = 0; j < 4; j++) sc[i][j] = 0.f;
        for (int kk = 0; kk < 128; kk++) {
            float4 a = *(const float4*)(Qs + kk * 64 + ty * 4);
            float4 b = *(const float4*)(Ks + kk * 64 + tx * 4);
            const float av[4] = {a.x, a.y, a.z, a.w};
            const float bv[4] = {b.x, b.y, b.z, b.w};
            #pragma unroll
            for (int i = 0; i < 4; i++)
                #pragma unroll
                for (int j = 0; j < 4; j++)
                    sc[i][j] = fmaf(av[i], bv[j], sc[i][j]);
        }
        // scale + causal mask (only diagonal tile needs it)
        #pragma unroll
        for (int i = 0; i < 4; i++)
            #pragma unroll
            for (int j = 0; j < 4; j++) {
                sc[i][j] *= scale;
                if (kb == qb && (kb * 64 + tx * 4 + j) > (qr0 + ty * 4 + i))
                    sc[i][j] = -1e30f;
            }

        // online softmax per row (16-lane half-warp reductions)
        #pragma unroll
        for (int i = 0; i < 4; i++) {
            float mloc = fmaxf(fmaxf(sc[i][0], sc[i][1]), fmaxf(sc[i][2], sc[i][3]));
            #pragma unroll
            for (int off = 8; off > 0; off >>= 1)
                mloc = fmaxf(mloc, __shfl_xor_sync(0xffffffffu, mloc, off));
            const float mnew = fmaxf(m_i[i], mloc);
            const float al = __expf(m_i[i] - mnew);
            const float p0 = __expf(sc[i][0] - mnew);
            const float p1 = __expf(sc[i][1] - mnew);
            const float p2 = __expf(sc[i][2] - mnew);
            const float p3 = __expf(sc[i][3] - mnew);
            float rs = p0 + p1 + p2 + p3;
            #pragma unroll
            for (int off = 8; off > 0; off >>= 1)
                rs += __shfl_xor_sync(0xffffffffu, rs, off);
            m_i[i] = mnew;
            l_i[i] = l_i[i] * al + rs;
            #pragma unroll
            for (int j = 0; j < 8; j++) acc[i][j] *= al;
            float* pr = Ps + (ty * 4 + i) * 64 + tx * 4;
            pr[0] = p0; pr[1] = p1; pr[2] = p2; pr[3] = p3;
        }
        __syncthreads();

        // O += P @ V
        #pragma unroll 4
        for (int j = 0; j < 64; j++) {
            const float a0 = Ps[(ty * 4 + 0) * 64 + j];
            const float a1 = Ps[(ty * 4 + 1) * 64 + j];
            const float a2 = Ps[(ty * 4 + 2) * 64 + j];
            const float a3 = Ps[(ty * 4 + 3) * 64 + j];
            float4 b0 = *(const float4*)(Vs + j * 128 + tx * 8);
            float4 b1 = *(const float4*)(Vs + j * 128 + tx * 8 + 4);
            const float bv[8] = {b0.x, b0.y, b0.z, b0.w, b1.x, b1.y, b1.z, b1.w};
            #pragma unroll
            for (int jj = 0; jj < 8; jj++) {
                acc[0][jj] = fmaf(a0, bv[jj], acc[0][jj]);
                acc[1][jj] = fmaf(a1, bv[jj], acc[1][jj]);
                acc[2][jj] = fmaf(a2, bv[jj], acc[2][jj]);
                acc[3][jj] = fmaf(a3, bv[jj], acc[3][jj]);
            }
        }
    }

    #pragma unroll
    for (int i = 0; i < 4; i++) {
        const float inv = 1.f / l_i[i];
        const int gr = qr0 + ty * 4 + i;
        float* Og = O + (size_t)gr * DM + head * 128 + tx * 8;
        float4 o0 = {acc[i][0] * inv, acc[i][1] * inv, acc[i][2] * inv, acc[i][3] * inv};
        float4 o1 = {acc[i][4] * inv, acc[i][5] * inv, acc[i][6] * inv, acc[i][7] * inv};
        *(float4*)Og = o0;
        *(float4*)(Og + 4) = o1;
    }
}

// ---------------- SwiGLU: G = silu(G) * U, in place ----------------
__global__ void silu_mul_kernel(float* __restrict__ G, const float* __restrict__ U, int n4)
{
    const int i = blockIdx.x * blockDim.x + threadIdx.x;
    if (i >= n4) return;
    float4 g = ((const float4*)G)[i];
    float4 u = ((const float4*)U)[i];
    g.x = g.x / (1.f + __expf(-g.x)) * u.x;
    g.y = g.y / (1.f + __expf(-g.y)) * u.y;
    g.z = g.z / (1.f + __expf(-g.z)) * u.z;
    g.w = g.w / (1.f + __expf(-g.w)) * u.w;
    ((float4*)G)[i] = g;
}

// ---------------- launcher ----------------
extern "C" void kernel_launch(void* const* d_in, const int* in_sizes, int n_in,
                              void* d_out, int out_size)
{
    const float* data      = (const float*)d_in[0];
    // d_in[1] = mask (exactly causal -1e9; implemented as hard causal)
    const float* cosp      = (const float*)d_in[2];
    const float* sinp      = (const float*)d_in[3];
    const float* attn_norm = (const float*)d_in[4];
    const float* wq        = (const float*)d_in[5];
    const float* wk        = (const float*)d_in[6];
    const float* wv        = (const float*)d_in[7];
    const float* wo        = (const float*)d_in[8];
    const float* wq_a      = (const float*)d_in[9];
    const float* wq_b      = (const float*)d_in[10];
    const float* wk_a      = (const float*)d_in[11];
    const float* wk_b      = (const float*)d_in[12];
    const float* wv_a      = (const float*)d_in[13];
    const float* wv_b      = (const float*)d_in[14];
    const float* wo_a      = (const float*)d_in[15];
    const float* wo_b      = (const float*)d_in[16];
    const float* ffn_norm  = (const float*)d_in[17];
    const float* w1        = (const float*)d_in[18];
    const float* w2        = (const float*)d_in[19];
    const float* w3        = (const float*)d_in[20];
    const float* w1_a      = (const float*)d_in[21];
    const float* w1_b      = (const float*)d_in[22];
    const float* w2_a      = (const float*)d_in[23];
    const float* w2_b      = (const float*)d_in[24];
    const float* w3_a      = (const float*)d_in[25];
    const float* w3_b      = (const float*)d_in[26];
    float* out = (float*)d_out;

    float *h, *q, *k, *v, *attn, *res2, *gate, *up, *tmp;
    cudaGetSymbolAddress((void**)&h, g_h);
    cudaGetSymbolAddress((void**)&q, g_q);
    cudaGetSymbolAddress((void**)&k, g_k);
    cudaGetSymbolAddress((void**)&v, g_v);
    cudaGetSymbolAddress((void**)&attn, g_attn);
    cudaGetSymbolAddress((void**)&res2, g_res2);
    cudaGetSymbolAddress((void**)&gate, g_gate);
    cudaGetSymbolAddress((void**)&up, g_up);
    cudaGetSymbolAddress((void**)&tmp, g_tmp);

    cudaFuncSetAttribute(flash_kernel, cudaFuncAttributeMaxDynamicSharedMemorySize, 114688);

    // ---- attention block ----
    rmsnorm_kernel<<<SLEN, 256>>>(data, attn_norm, h, DM);

    lora_tmp_kernel<<<SLEN, 512>>>(h, wq_a, tmp, DM);
    sgemm_lora<<<dim3(DM / 128, SLEN / 128), 256>>>(h, wq, tmp, wq_b, nullptr, q, SLEN, DM, DM);
    rope_kernel<<<(SLEN * 32 * 64) / 256, 256>>>(q, cosp, sinp, 32, SLEN * 32 * 64);

    lora_tmp_kernel<<<SLEN, 512>>>(h, wk_a, tmp, DM);
    sgemm_lora<<<dim3(KVDIM / 128, SLEN / 128), 256>>>(h, wk, tmp, wk_b, nullptr, k, SLEN, KVDIM, DM);
    rope_kernel<<<(SLEN * 8 * 64) / 256, 256>>>(k, cosp, sinp, 8, SLEN * 8 * 64);

    lora_tmp_kernel<<<SLEN, 512>>>(h, wv_a, tmp, DM);
    sgemm_lora<<<dim3(KVDIM / 128, SLEN / 128), 256>>>(h, wv, tmp, wv_b, nullptr, v, SLEN, KVDIM, DM);

    flash_kernel<<<dim3(SLEN / 64, 32), 256, 114688>>>(q, k, v, attn);

    lora_tmp_kernel<<<SLEN, 512>>>(attn, wo_a, tmp, DM);
    sgemm_lora<<<dim3(DM / 128, SLEN / 128), 256>>>(attn, wo, tmp, wo_b, data, res2, SLEN, DM, DM);

    // ---- FFN block ----
    rmsnorm_kernel<<<SLEN, 256>>>(res2, ffn_norm, h, DM);

    lora_tmp_kernel<<<SLEN, 512>>>(h, w1_a, tmp, DM);
    sgemm_lora<<<dim3(FF / 128, SLEN / 128), 256>>>(h, w1, tmp, w1_b, nullptr, gate, SLEN, FF, DM);

    lora_tmp_kernel<<<SLEN, 512>>>(h, w3_a, tmp, DM);
    sgemm_lora<<<dim3(FF / 128, SLEN / 128), 256>>>(h, w3, tmp, w3_b, nullptr, up, SLEN, FF, DM);

    silu_mul_kernel<<<(SLEN * FF / 4) / 256, 256>>>(gate, up, SLEN * FF / 4);

    lora_tmp_kernel<<<SLEN, 512>>>(gate, w2_a, tmp, FF);
    sgemm_lora<<<dim3(DM / 128, SLEN / 128), 256>>>(gate, w2, tmp, w2_b, res2, out, SLEN, DM, FF);
}

// round 8
// speedup vs baseline: 3.1513x; 3.1513x over previous
#include <cuda_runtime.h>
#include <cstdint>

#define SLEN  1024
#define DM    4096
#define FF    14336
#define KVDIM 1024
#define RLORA 16
#define LSCALE 2.0f

// ---------------- scratch (device globals; no allocations) ----------------
__device__ float g_h[SLEN * DM];
__device__ float g_q[SLEN * DM];
__device__ float g_k[SLEN * KVDIM];
__device__ float g_v[SLEN * KVDIM];
__device__ float g_attn[SLEN * DM];
__device__ float g_res2[SLEN * DM];
__device__ float g_gate[SLEN * FF];
__device__ float g_up[SLEN * FF];
__device__ float g_tmp[SLEN * RLORA];

// ======================= helpers =======================
__device__ __forceinline__ uint32_t smem_u32(const void* p) {
    uint32_t a;
    asm("{ .reg .u64 t; cvta.to.shared.u64 t, %1; cvt.u32.u64 %0, t; }" : "=r"(a) : "l"(p));
    return a;
}
__device__ __forceinline__ uint32_t to_tf32(float f) {
    uint32_t u;
    asm("cvt.rna.tf32.f32 %0, %1;" : "=r"(u) : "f"(f));
    return u;
}
// swizzled float index inside a [128][32] fp32 tile (float4-group XOR row&7)
__device__ __forceinline__ int swi(int row, int k) {
    return row * 32 + ((((k) >> 2) ^ (row & 7)) << 2) + (k & 3);
}

// ======================= tf32 mma.sync GEMM =======================
// C[M,N] = A[M,K] @ B[N,K]^T + T[M,16] @ Bl[N,16]^T (+ Res)
// (LoRA scale pre-folded into T.) 128x128 tile/CTA, BK=32, 2-stage cp.async.
// 256 threads = 8 warps in 2(m) x 4(n) grid, warp tile 64x32, mma m16n8k8.
// grid = (M/128, N/128); dynamic smem = 2 * (16K + 16K) = 65536 bytes.
__global__ __launch_bounds__(256, 2) void gemm_tc(
    const float* __restrict__ A, const float* __restrict__ B,
    const float* __restrict__ T, const float* __restrict__ Bl,
    const float* __restrict__ Res, float* __restrict__ C,
    int M, int N, int K)
{
    extern __shared__ float smf[];
    const uint32_t sbase = smem_u32(smf);
    const int tid = threadIdx.x;
    const int wid = tid >> 5, lane = tid & 31;
    const int gid = lane >> 2, tig = lane & 3;     // group id / thread-in-group
    const int wm = wid >> 2, wn = wid & 3;          // warp grid 2 x 4
    const int m0 = blockIdx.x << 7, n0 = blockIdx.y << 7;

    const int KT = K >> 5;        // 32-wide K tiles
    const int TT = KT + 1;        // + LoRA tile

    float acc[4][4][4];
    #pragma unroll
    for (int i = 0; i < 4; i++)
        #pragma unroll
        for (int j = 0; j < 4; j++)
            #pragma unroll
            for (int c = 0; c < 4; c++) acc[i][j][c] = 0.f;

    const float* Ag = A + (size_t)m0 * K;
    const float* Bg = B + (size_t)n0 * K;

    // ---- tile loaders ----
    // buffer b: A at floats [b*8192, +4096), B at [b*8192+4096, +4096)
    #define CP_TILE(t, b)                                                            \
    do {                                                                             \
        const int k0 = (t) << 5;                                                     \
        const uint32_t ab = sbase + (uint32_t)(b) * 32768u;                          \
        const uint32_t bb = ab + 16384u;                                             \
        _Pragma("unroll")                                                            \
        for (int it = 0; it < 4; it++) {                                             \
            const int li = it * 256 + tid;                                           \
            const int row = li >> 3, g = li & 7;                                     \
            const uint32_t off = (uint32_t)(row * 128 + ((g ^ (row & 7)) << 4));     \
            const float* sa = Ag + (size_t)row * K + k0 + g * 4;                     \
            const float* sb = Bg + (size_t)row * K + k0 + g * 4;                     \
            asm volatile("cp.async.cg.shared.global [%0], [%1], 16;"                 \
                         :: "r"(ab + off), "l"(sa));                                 \
            asm volatile("cp.async.cg.shared.global [%0], [%1], 16;"                 \
                         :: "r"(bb + off), "l"(sb));                                 \
        }                                                                            \
        asm volatile("cp.async.commit_group;");                                      \
    } while (0)

    #define LORA_TILE(b)                                                             \
    do {                                                                             \
        float* ap = smf + (b) * 8192;                                                \
        float* bp = ap + 4096;                                                       \
        _Pragma("unroll")                                                            \
        for (int it = 0; it < 4; it++) {                                             \
            const int li = it * 256 + tid;                                           \
            const int row = li >> 3, g = li & 7;                                     \
            const int idx = row * 32 + ((g ^ (row & 7)) << 2);                       \
            float4 va = make_float4(0.f, 0.f, 0.f, 0.f);                             \
            float4 vb = make_float4(0.f, 0.f, 0.f, 0.f);                             \
            if (g < 4) {                                                             \
                va = *(const float4*)(T  + (size_t)(m0 + row) * RLORA + g * 4);      \
                vb = *(const float4*)(Bl + (size_t)(n0 + row) * RLORA + g * 4);      \
            }                                                                        \
            *(float4*)(ap + idx) = va;                                               \
            *(float4*)(bp + idx) = vb;                                               \
        }                                                                            \
    } while (0)

    // prologue: tile 0 (always a cp tile; K >= 32)
    CP_TILE(0, 0);

    for (int t = 0; t < TT; t++) {
        // prefetch t+1 into the other buffer.
        // Buffer (t+1)&1 was last consumed by tile t-1's MMA phase, which
        // completed before the __syncthreads() at the end of iteration t-1,
        // so writing it here is race-free for the LORA (direct-store) path too.
        if (t + 1 < TT) {
            if (t + 1 < KT) CP_TILE(t + 1, (t + 1) & 1);
            else            LORA_TILE((t + 1) & 1);
        }
        // wait for the cp.async group that filled buffer t&1
        if (t + 1 < KT) asm volatile("cp.async.wait_group 1;" ::: "memory");
        else            asm volatile("cp.async.wait_group 0;" ::: "memory");
        __syncthreads();

        const float* As = smf + (t & 1) * 8192;
        const float* Bs = As + 4096;

        #pragma unroll
        for (int s = 0; s < 4; s++) {
            const int kb = s * 8;
            uint32_t af[4][4], bf[4][2];
            #pragma unroll
            for (int mi = 0; mi < 4; mi++) {
                const int r0 = wm * 64 + mi * 16 + gid;
                af[mi][0] = to_tf32(As[swi(r0,     kb + tig)]);
                af[mi][1] = to_tf32(As[swi(r0 + 8, kb + tig)]);
                af[mi][2] = to_tf32(As[swi(r0,     kb + tig + 4)]);
                af[mi][3] = to_tf32(As[swi(r0 + 8, kb + tig + 4)]);
            }
            #pragma unroll
            for (int nj = 0; nj < 4; nj++) {
                const int nr = wn * 32 + nj * 8 + gid;
                bf[nj][0] = to_tf32(Bs[swi(nr, kb + tig)]);
                bf[nj][1] = to_tf32(Bs[swi(nr, kb + tig + 4)]);
            }
            #pragma unroll
            for (int mi = 0; mi < 4; mi++)
                #pragma unroll
                for (int nj = 0; nj < 4; nj++) {
                    asm volatile(
                        "mma.sync.aligned.m16n8k8.row.col.f32.tf32.tf32.f32 "
                        "{%0,%1,%2,%3}, {%4,%5,%6,%7}, {%8,%9}, {%0,%1,%2,%3};"
                        : "+f"(acc[mi][nj][0]), "+f"(acc[mi][nj][1]),
                          "+f"(acc[mi][nj][2]), "+f"(acc[mi][nj][3])
                        : "r"(af[mi][0]), "r"(af[mi][1]), "r"(af[mi][2]), "r"(af[mi][3]),
                          "r"(bf[nj][0]), "r"(bf[nj][1]));
                }
        }
        __syncthreads();
    }

    // ---- epilogue: fp32 accum -> (+Res) -> C ----
    #pragma unroll
    for (int mi = 0; mi < 4; mi++) {
        const int gr0 = m0 + wm * 64 + mi * 16 + gid;
        #pragma unroll
        for (int nj = 0; nj < 4; nj++) {
            const int gc = n0 + wn * 32 + nj * 8 + tig * 2;
            const size_t i0 = (size_t)gr0 * N + gc;
            const size_t i1 = (size_t)(gr0 + 8) * N + gc;
            float2 o0 = {acc[mi][nj][0], acc[mi][nj][1]};
            float2 o1 = {acc[mi][nj][2], acc[mi][nj][3]};
            if (Res) {
                float2 r0 = *(const float2*)(Res + i0);
                float2 r1 = *(const float2*)(Res + i1);
                o0.x += r0.x; o0.y += r0.y;
                o1.x += r1.x; o1.y += r1.y;
            }
            *(float2*)(C + i0) = o0;
            *(float2*)(C + i1) = o1;
        }
    }
}

// ---------------- rmsnorm: one block per row ----------------
__global__ void rmsnorm_kernel(const float* __restrict__ X, const float* __restrict__ W,
                               float* __restrict__ Y, int D)
{
    const int m = blockIdx.x, tid = threadIdx.x;   // 256 threads
    const float* x = X + (size_t)m * D;
    float s = 0.f;
    for (int k = tid * 4; k < D; k += 1024) {
        float4 v = *(const float4*)(x + k);
        s += v.x * v.x + v.y * v.y + v.z * v.z + v.w * v.w;
    }
    __shared__ float red[9];
    #pragma unroll
    for (int off = 16; off > 0; off >>= 1) s += __shfl_xor_sync(0xffffffffu, s, off);
    if ((tid & 31) == 0) red[tid >> 5] = s;
    __syncthreads();
    if (tid == 0) {
        float t = 0.f;
        #pragma unroll
        for (int i = 0; i < 8; i++) t += red[i];
        red[8] = rsqrtf(t / (float)D + 1e-5f);
    }
    __syncthreads();
    const float inv = red[8];
    float* y = Y + (size_t)m * D;
    for (int k = tid * 4; k < D; k += 1024) {
        float4 v = *(const float4*)(x + k);
        float4 w = *(const float4*)(W + k);
        v.x = v.x * inv * w.x;
        v.y = v.y * inv * w.y;
        v.z = v.z * inv * w.z;
        v.w = v.w * inv * w.w;
        *(float4*)(y + k) = v;
    }
}

// ---------------- LoRA down-projection: T[M,16] = LSCALE * X[M,K] @ A[16,K]^T ----------------
__global__ void lora_tmp_kernel(const float* __restrict__ X, const float* __restrict__ Aw,
                                float* __restrict__ T, int K)
{
    const int m = blockIdx.x;
    const int w = threadIdx.x >> 5, lane = threadIdx.x & 31;
    const float* x = X + (size_t)m * K;
    const float* a = Aw + (size_t)w * K;
    float s = 0.f;
    for (int k = lane * 4; k < K; k += 128) {
        float4 xv = *(const float4*)(x + k);
        float4 av = *(const float4*)(a + k);
        s += xv.x * av.x + xv.y * av.y + xv.z * av.z + xv.w * av.w;
    }
    #pragma unroll
    for (int off = 16; off > 0; off >>= 1) s += __shfl_xor_sync(0xffffffffu, s, off);
    if (lane == 0) T[m * RLORA + w] = s * LSCALE;
}

// ---------------- RoPE (interleaved pairs), in place ----------------
__global__ void rope_kernel(float* __restrict__ X, const float* __restrict__ Cc,
                            const float* __restrict__ Sn, int H, int total)
{
    const int idx = blockIdx.x * blockDim.x + threadIdx.x;
    if (idx >= total) return;
    const int i = idx & 63;
    const int rest = idx >> 6;
    const int h = rest % H;
    const int s = rest / H;
    const float c = Cc[s * 64 + i], sn = Sn[s * 64 + i];
    float* p = X + (size_t)s * (H * 128) + h * 128 + 2 * i;
    const float x1 = p[0], x2 = p[1];
    p[0] = x1 * c - x2 * sn;
    p[1] = x1 * sn + x2 * c;
}

// ---------------- flash attention fp32: 64x64 tiles, causal, GQA 4:1 ----------------
__global__ __launch_bounds__(256) void flash_kernel(
    const float* __restrict__ Q, const float* __restrict__ Kk,
    const float* __restrict__ V, float* __restrict__ O)
{
    extern __shared__ float smf[];
    float* Qs = smf;
    float* Ks = smf + 128 * 64;
    float* Vs = smf + 2 * 128 * 64;
    float* Ps = smf + 3 * 128 * 64;

    const int qb = blockIdx.x, head = blockIdx.y;
    const int kvh = head >> 2;
    const int tid = threadIdx.x;
    const int ty = tid >> 4, tx = tid & 15;
    const int qr0 = qb * 64;

    const float* Qg = Q + (size_t)qr0 * DM + head * 128;
    for (int li = tid; li < 2048; li += 256) {
        const int r = li >> 5, c4 = li & 31;
        float4 v = *(const float4*)(Qg + (size_t)r * DM + c4 * 4);
        Qs[(c4 * 4 + 0) * 64 + r] = v.x;
        Qs[(c4 * 4 + 1) * 64 + r] = v.y;
        Qs[(c4 * 4 + 2) * 64 + r] = v.z;
        Qs[(c4 * 4 + 3) * 64 + r] = v.w;
    }

    float m_i[4], l_i[4], acc[4][8];
    #pragma unroll
    for (int i = 0; i < 4; i++) {
        m_i[i] = -1e30f; l_i[i] = 0.f;
        #pragma unroll
        for (int j = 0; j < 8; j++) acc[i][j] = 0.f;
    }
    const float scale = 0.088388347648318447f;

    for (int kb = 0; kb <= qb; kb++) {
        __syncthreads();
        const float* Kg = Kk + (size_t)(kb * 64) * KVDIM + kvh * 128;
        const float* Vg = V + (size_t)(kb * 64) * KVDIM + kvh * 128;
        for (int li = tid; li < 2048; li += 256) {
            const int r = li >> 5, c4 = li & 31;
            float4 kv = *(const float4*)(Kg + (size_t)r * KVDIM + c4 * 4);
            Ks[(c4 * 4 + 0) * 64 + r] = kv.x;
            Ks[(c4 * 4 + 1) * 64 + r] = kv.y;
            Ks[(c4 * 4 + 2) * 64 + r] = kv.z;
            Ks[(c4 * 4 + 3) * 64 + r] = kv.w;
            float4 vv = *(const float4*)(Vg + (size_t)r * KVDIM + c4 * 4);
            *(float4*)(Vs + r * 128 + c4 * 4) = vv;
        }
        __syncthreads();

        float sc[4][4];
        #pragma unroll
        for (int i = 0; i < 4; i++)
            #pragma unroll
            for (int j = 0; j < 4; j++) sc[i][j] = 0.f;
        for (int kk = 0; kk < 128; kk++) {
            float4 a = *(const float4*)(Qs + kk * 64 + ty * 4);
            float4 b = *(const float4*)(Ks + kk * 64 + tx * 4);
            const float av[4] = {a.x, a.y, a.z, a.w};
            const float bv[4] = {b.x, b.y, b.z, b.w};
            #pragma unroll
            for (int i = 0; i < 4; i++)
                #pragma unroll
                for (int j = 0; j < 4; j++)
                    sc[i][j] = fmaf(av[i], bv[j], sc[i][j]);
        }
        #pragma unroll
        for (int i = 0; i < 4; i++)
            #pragma unroll
            for (int j = 0; j < 4; j++) {
                sc[i][j] *= scale;
                if (kb == qb && (kb * 64 + tx * 4 + j) > (qr0 + ty * 4 + i))
                    sc[i][j] = -1e30f;
            }

        #pragma unroll
        for (int i = 0; i < 4; i++) {
            float mloc = fmaxf(fmaxf(sc[i][0], sc[i][1]), fmaxf(sc[i][2], sc[i][3]));
            #pragma unroll
            for (int off = 8; off > 0; off >>= 1)
                mloc = fmaxf(mloc, __shfl_xor_sync(0xffffffffu, mloc, off));
            const float mnew = fmaxf(m_i[i], mloc);
            const float al = __expf(m_i[i] - mnew);
            const float p0 = __expf(sc[i][0] - mnew);
            const float p1 = __expf(sc[i][1] - mnew);
            const float p2 = __expf(sc[i][2] - mnew);
            const float p3 = __expf(sc[i][3] - mnew);
            float rs = p0 + p1 + p2 + p3;
            #pragma unroll
            for (int off = 8; off > 0; off >>= 1)
                rs += __shfl_xor_sync(0xffffffffu, rs, off);
            m_i[i] = mnew;
            l_i[i] = l_i[i] * al + rs;
            #pragma unroll
            for (int j = 0; j < 8; j++) acc[i][j] *= al;
            float* pr = Ps + (ty * 4 + i) * 64 + tx * 4;
            pr[0] = p0; pr[1] = p1; pr[2] = p2; pr[3] = p3;
        }
        __syncthreads();

        #pragma unroll 4
        for (int j = 0; j < 64; j++) {
            const float a0 = Ps[(ty * 4 + 0) * 64 + j];
            const float a1 = Ps[(ty * 4 + 1) * 64 + j];
            const float a2 = Ps[(ty * 4 + 2) * 64 + j];
            const float a3 = Ps[(ty * 4 + 3) * 64 + j];
            float4 b0 = *(const float4*)(Vs + j * 128 + tx * 8);
            float4 b1 = *(const float4*)(Vs + j * 128 + tx * 8 + 4);
            const float bv[8] = {b0.x, b0.y, b0.z, b0.w, b1.x, b1.y, b1.z, b1.w};
            #pragma unroll
            for (int jj = 0; jj < 8; jj++) {
                acc[0][jj] = fmaf(a0, bv[jj], acc[0][jj]);
                acc[1][jj] = fmaf(a1, bv[jj], acc[1][jj]);
                acc[2][jj] = fmaf(a2, bv[jj], acc[2][jj]);
                acc[3][jj] = fmaf(a3, bv[jj], acc[3][jj]);
            }
        }
    }

    #pragma unroll
    for (int i = 0; i < 4; i++) {
        const float inv = 1.f / l_i[i];
        const int gr = qr0 + ty * 4 + i;
        float* Og = O + (size_t)gr * DM + head * 128 + tx * 8;
        float4 o0 = {acc[i][0] * inv, acc[i][1] * inv, acc[i][2] * inv, acc[i][3] * inv};
        float4 o1 = {acc[i][4] * inv, acc[i][5] * inv, acc[i][6] * inv, acc[i][7] * inv};
        *(float4*)Og = o0;
        *(float4*)(Og + 4) = o1;
    }
}

// ---------------- SwiGLU: G = silu(G) * U, in place ----------------
__global__ void silu_mul_kernel(float* __restrict__ G, const float* __restrict__ U, int n4)
{
    const int i = blockIdx.x * blockDim.x + threadIdx.x;
    if (i >= n4) return;
    float4 g = ((const float4*)G)[i];
    float4 u = ((const float4*)U)[i];
    g.x = g.x / (1.f + __expf(-g.x)) * u.x;
    g.y = g.y / (1.f + __expf(-g.y)) * u.y;
    g.z = g.z / (1.f + __expf(-g.z)) * u.z;
    g.w = g.w / (1.f + __expf(-g.w)) * u.w;
    ((float4*)G)[i] = g;
}

// ---------------- launcher ----------------
#define GEMM_SMEM 65536

extern "C" void kernel_launch(void* const* d_in, const int* in_sizes, int n_in,
                              void* d_out, int out_size)
{
    const float* data      = (const float*)d_in[0];
    const float* cosp      = (const float*)d_in[2];
    const float* sinp      = (const float*)d_in[3];
    const float* attn_norm = (const float*)d_in[4];
    const float* wq        = (const float*)d_in[5];
    const float* wk        = (const float*)d_in[6];
    const float* wv        = (const float*)d_in[7];
    const float* wo        = (const float*)d_in[8];
    const float* wq_a      = (const float*)d_in[9];
    const float* wq_b      = (const float*)d_in[10];
    const float* wk_a      = (const float*)d_in[11];
    const float* wk_b      = (const float*)d_in[12];
    const float* wv_a      = (const float*)d_in[13];
    const float* wv_b      = (const float*)d_in[14];
    const float* wo_a      = (const float*)d_in[15];
    const float* wo_b      = (const float*)d_in[16];
    const float* ffn_norm  = (const float*)d_in[17];
    const float* w1        = (const float*)d_in[18];
    const float* w2        = (const float*)d_in[19];
    const float* w3        = (const float*)d_in[20];
    const float* w1_a      = (const float*)d_in[21];
    const float* w1_b      = (const float*)d_in[22];
    const float* w2_a      = (const float*)d_in[23];
    const float* w2_b      = (const float*)d_in[24];
    const float* w3_a      = (const float*)d_in[25];
    const float* w3_b      = (const float*)d_in[26];
    float* out = (float*)d_out;

    float *h, *q, *k, *v, *attn, *res2, *gate, *up, *tmp;
    cudaGetSymbolAddress((void**)&h, g_h);
    cudaGetSymbolAddress((void**)&q, g_q);
    cudaGetSymbolAddress((void**)&k, g_k);
    cudaGetSymbolAddress((void**)&v, g_v);
    cudaGetSymbolAddress((void**)&attn, g_attn);
    cudaGetSymbolAddress((void**)&res2, g_res2);
    cudaGetSymbolAddress((void**)&gate, g_gate);
    cudaGetSymbolAddress((void**)&up, g_up);
    cudaGetSymbolAddress((void**)&tmp, g_tmp);

    cudaFuncSetAttribute(flash_kernel, cudaFuncAttributeMaxDynamicSharedMemorySize, 114688);
    cudaFuncSetAttribute(gemm_tc, cudaFuncAttributeMaxDynamicSharedMemorySize, GEMM_SMEM);

    // ---- attention block ----
    rmsnorm_kernel<<<SLEN, 256>>>(data, attn_norm, h, DM);

    lora_tmp_kernel<<<SLEN, 512>>>(h, wq_a, tmp, DM);
    gemm_tc<<<dim3(SLEN / 128, DM / 128), 256, GEMM_SMEM>>>(h, wq, tmp, wq_b, nullptr, q, SLEN, DM, DM);
    rope_kernel<<<(SLEN * 32 * 64) / 256, 256>>>(q, cosp, sinp, 32, SLEN * 32 * 64);

    lora_tmp_kernel<<<SLEN, 512>>>(h, wk_a, tmp, DM);
    gemm_tc<<<dim3(SLEN / 128, KVDIM / 128), 256, GEMM_SMEM>>>(h, wk, tmp, wk_b, nullptr, k, SLEN, KVDIM, DM);
    rope_kernel<<<(SLEN * 8 * 64) / 256, 256>>>(k, cosp, sinp, 8, SLEN * 8 * 64);

    lora_tmp_kernel<<<SLEN, 512>>>(h, wv_a, tmp, DM);
    gemm_tc<<<dim3(SLEN / 128, KVDIM / 128), 256, GEMM_SMEM>>>(h, wv, tmp, wv_b, nullptr, v, SLEN, KVDIM, DM);

    flash_kernel<<<dim3(SLEN / 64, 32), 256, 114688>>>(q, k, v, attn);

    lora_tmp_kernel<<<SLEN, 512>>>(attn, wo_a, tmp, DM);
    gemm_tc<<<dim3(SLEN / 128, DM / 128), 256, GEMM_SMEM>>>(attn, wo, tmp, wo_b, data, res2, SLEN, DM, DM);

    // ---- FFN block ----
    rmsnorm_kernel<<<SLEN, 256>>>(res2, ffn_norm, h, DM);

    lora_tmp_kernel<<<SLEN, 512>>>(h, w1_a, tmp, DM);
    gemm_tc<<<dim3(SLEN / 128, FF / 128), 256, GEMM_SMEM>>>(h, w1, tmp, w1_b, nullptr, gate, SLEN, FF, DM);

    lora_tmp_kernel<<<SLEN, 512>>>(h, w3_a, tmp, DM);
    gemm_tc<<<dim3(SLEN / 128, FF / 128), 256, GEMM_SMEM>>>(h, w3, tmp, w3_b, nullptr, up, SLEN, FF, DM);

    silu_mul_kernel<<<(SLEN * FF / 4) / 256, 256>>>(gate, up, SLEN * FF / 4);

    lora_tmp_kernel<<<SLEN, 512>>>(gate, w2_a, tmp, FF);
    gemm_tc<<<dim3(SLEN / 128, DM / 128), 256, GEMM_SMEM>>>(gate, w2, tmp, w2_b, res2, out, SLEN, DM, FF);
}

// round 12
// speedup vs baseline: 5.6116x; 1.7807x over previous
#include <cuda_runtime.h>
#include <cuda_fp16.h>
#include <cstdint>

#define SLEN  1024
#define DM    4096
#define FF    14336
#define KVDIM 1024
#define RLORA 16
#define LSCALE 2.0f

// ---------------- scratch (device globals; no allocations) ----------------
__device__ float g_h[SLEN * DM];
__device__ float g_q[SLEN * DM];
__device__ float g_k[SLEN * KVDIM];
__device__ float g_v[SLEN * KVDIM];
__device__ float g_attn[SLEN * DM];
__device__ float g_res2[SLEN * DM];
__device__ float g_gate[SLEN * FF];
__device__ float g_up[SLEN * FF];
__device__ float g_tmp[SLEN * RLORA];

// fp16 mirrors
__device__ __half g_wq_h[DM * DM];
__device__ __half g_wk_h[KVDIM * DM];
__device__ __half g_wv_h[KVDIM * DM];
__device__ __half g_wo_h[DM * DM];
__device__ __half g_w1_h[FF * DM];
__device__ __half g_w3_h[FF * DM];
__device__ __half g_w2_h[DM * FF];
__device__ __half g_h_h[SLEN * DM];
__device__ __half g_attn_h[SLEN * DM];
__device__ __half g_gu_h[SLEN * FF];

// ======================= helpers =======================
__device__ __forceinline__ uint32_t smem_u32(const void* p) {
    uint32_t a;
    asm("{ .reg .u64 t; cvta.to.shared.u64 t, %1; cvt.u32.u64 %0, t; }" : "=r"(a) : "l"(p));
    return a;
}
__device__ __forceinline__ uint32_t pack_h2(float a, float b) {
    __half2 h = __floats2half2_rn(a, b);
    return *(uint32_t*)&h;
}
// swizzled byte offset inside a [128 rows][64 halfs] tile (16B-group XOR row&7)
__device__ __forceinline__ uint32_t swb(int row, int k) {
    return (uint32_t)(row * 128 + (((k >> 3) ^ (row & 7)) << 4) + (k & 7) * 2);
}
__device__ __forceinline__ uint32_t lds_h2(const char* base, int row, int k) {
    return *(const uint32_t*)(base + swb(row, k));
}

// ---------------- fp32 -> fp16 conversion ----------------
__global__ void f2h_kernel(const float* __restrict__ X, __half* __restrict__ Y, int n4)
{
    const int i = blockIdx.x * blockDim.x + threadIdx.x;
    if (i >= n4) return;
    float4 v = ((const float4*)X)[i];
    __half2 a = __floats2half2_rn(v.x, v.y);
    __half2 b = __floats2half2_rn(v.z, v.w);
    ((__half2*)Y)[2 * i]     = a;
    ((__half2*)Y)[2 * i + 1] = b;
}

// ======================= fp16 mma.sync GEMM =======================
// C[M,N] = A[M,K] @ B[N,K]^T + T[M,16] @ Bl[N,16]^T (+ Res)
// A,B fp16; T,Bl,Res,C fp32. LoRA scale pre-folded into T.
// 128x128 tile/CTA, BK=64 halfs, 2-stage cp.async.
// 256 threads = 8 warps in 2(m) x 4(n) grid, warp tile 64x32, mma m16n8k16.
// grid = (M/128, N/128); dynamic smem = 2 * (16K + 16K) = 65536 bytes.
__global__ __launch_bounds__(256, 2) void gemm_fp16(
    const __half* __restrict__ A, const __half* __restrict__ B,
    const float* __restrict__ T, const float* __restrict__ Bl,
    const float* __restrict__ Res, float* __restrict__ C,
    int M, int N, int K)
{
    extern __shared__ char smc[];
    const uint32_t sbase = smem_u32(smc);
    const int tid = threadIdx.x;
    const int wid = tid >> 5, lane = tid & 31;
    const int gid = lane >> 2, tig = lane & 3;
    const int wm = wid >> 2, wn = wid & 3;          // warp grid 2 x 4
    const int m0 = blockIdx.x << 7, n0 = blockIdx.y << 7;

    const int KT = K >> 6;        // 64-wide K tiles
    const int TT = KT + 1;        // + LoRA tile

    float acc[4][4][4];
    #pragma unroll
    for (int i = 0; i < 4; i++)
        #pragma unroll
        for (int j = 0; j < 4; j++)
            #pragma unroll
            for (int c = 0; c < 4; c++) acc[i][j][c] = 0.f;

    const __half* Ag = A + (size_t)m0 * K;
    const __half* Bg = B + (size_t)n0 * K;

    // buffer b: A tile at byte b*32768, B tile at +16384. 128 rows x 128B each.
    #define CP_TILE(t, b)                                                            \
    do {                                                                             \
        const int k0 = (t) << 6;                                                     \
        const uint32_t ab = sbase + (uint32_t)(b) * 32768u;                          \
        const uint32_t bb = ab + 16384u;                                             \
        _Pragma("unroll")                                                            \
        for (int it = 0; it < 4; it++) {                                             \
            const int li = it * 256 + tid;                                           \
            const int row = li >> 3, g = li & 7;                                     \
            const uint32_t off = (uint32_t)(row * 128 + ((g ^ (row & 7)) << 4));     \
            const __half* sa = Ag + (size_t)row * K + k0 + g * 8;                    \
            const __half* sb = Bg + (size_t)row * K + k0 + g * 8;                    \
            asm volatile("cp.async.cg.shared.global [%0], [%1], 16;"                 \
                         :: "r"(ab + off), "l"(sa));                                 \
            asm volatile("cp.async.cg.shared.global [%0], [%1], 16;"                 \
                         :: "r"(bb + off), "l"(sb));                                 \
        }                                                                            \
        asm volatile("cp.async.commit_group;");                                      \
    } while (0)

    // LoRA tile: halfs 0-15 from T / Bl (cvt fp32->fp16), 16-63 zero
    #define LORA_TILE(b)                                                             \
    do {                                                                             \
        char* ap = smc + (b) * 32768;                                                \
        char* bp = ap + 16384;                                                       \
        _Pragma("unroll")                                                            \
        for (int it = 0; it < 4; it++) {                                             \
            const int li = it * 256 + tid;                                           \
            const int row = li >> 3, g = li & 7;                                     \
            const uint32_t off = (uint32_t)(row * 128 + ((g ^ (row & 7)) << 4));     \
            uint4 ua = make_uint4(0, 0, 0, 0);                                       \
            uint4 ub = make_uint4(0, 0, 0, 0);                                       \
            if (g < 2) {                                                             \
                const float* ts = T  + (size_t)(m0 + row) * RLORA + g * 8;           \
                const float* bs = Bl + (size_t)(n0 + row) * RLORA + g * 8;           \
                float4 t0 = *(const float4*)ts;                                      \
                float4 t1 = *(const float4*)(ts + 4);                                \
                float4 b0 = *(const float4*)bs;                                      \
                float4 b1 = *(const float4*)(bs + 4);                                \
                ua = make_uint4(pack_h2(t0.x, t0.y), pack_h2(t0.z, t0.w),            \
                                pack_h2(t1.x, t1.y), pack_h2(t1.z, t1.w));           \
                ub = make_uint4(pack_h2(b0.x, b0.y), pack_h2(b0.z, b0.w),            \
                                pack_h2(b1.x, b1.y), pack_h2(b1.z, b1.w));           \
            }                                                                        \
            *(uint4*)(ap + off) = ua;                                                \
            *(uint4*)(bp + off) = ub;                                                \
        }                                                                            \
    } while (0)

    // prologue: tile 0 (always a cp tile; K >= 64)
    CP_TILE(0, 0);

    for (int t = 0; t < TT; t++) {
        if (t + 1 < TT) {
            if (t + 1 < KT) CP_TILE(t + 1, (t + 1) & 1);
            else            LORA_TILE((t + 1) & 1);
        }
        if (t + 1 < KT) asm volatile("cp.async.wait_group 1;" ::: "memory");
        else            asm volatile("cp.async.wait_group 0;" ::: "memory");
        __syncthreads();

        const char* As = smc + (t & 1) * 32768;
        const char* Bs = As + 16384;

        #pragma unroll
        for (int s = 0; s < 4; s++) {
            const int kb = s * 16;
            uint32_t af[4][4], bf[4][2];
            #pragma unroll
            for (int mi = 0; mi < 4; mi++) {
                const int r0 = wm * 64 + mi * 16 + gid;
                af[mi][0] = lds_h2(As, r0,     kb + 2 * tig);
                af[mi][1] = lds_h2(As, r0 + 8, kb + 2 * tig);
                af[mi][2] = lds_h2(As, r0,     kb + 8 + 2 * tig);
                af[mi][3] = lds_h2(As, r0 + 8, kb + 8 + 2 * tig);
            }
            #pragma unroll
            for (int nj = 0; nj < 4; nj++) {
                const int nr = wn * 32 + nj * 8 + gid;
                bf[nj][0] = lds_h2(Bs, nr, kb + 2 * tig);
                bf[nj][1] = lds_h2(Bs, nr, kb + 8 + 2 * tig);
            }
            #pragma unroll
            for (int mi = 0; mi < 4; mi++)
                #pragma unroll
                for (int nj = 0; nj < 4; nj++) {
                    asm volatile(
                        "mma.sync.aligned.m16n8k16.row.col.f32.f16.f16.f32 "
                        "{%0,%1,%2,%3}, {%4,%5,%6,%7}, {%8,%9}, {%0,%1,%2,%3};"
                        : "+f"(acc[mi][nj][0]), "+f"(acc[mi][nj][1]),
                          "+f"(acc[mi][nj][2]), "+f"(acc[mi][nj][3])
                        : "r"(af[mi][0]), "r"(af[mi][1]), "r"(af[mi][2]), "r"(af[mi][3]),
                          "r"(bf[nj][0]), "r"(bf[nj][1]));
                }
        }
        __syncthreads();
    }

    // ---- epilogue: fp32 accum -> (+Res) -> C ----
    #pragma unroll
    for (int mi = 0; mi < 4; mi++) {
        const int gr0 = m0 + wm * 64 + mi * 16 + gid;
        #pragma unroll
        for (int nj = 0; nj < 4; nj++) {
            const int gc = n0 + wn * 32 + nj * 8 + tig * 2;
            const size_t i0 = (size_t)gr0 * N + gc;
            const size_t i1 = (size_t)(gr0 + 8) * N + gc;
            float2 o0 = {acc[mi][nj][0], acc[mi][nj][1]};
            float2 o1 = {acc[mi][nj][2], acc[mi][nj][3]};
            if (Res) {
                float2 r0 = *(const float2*)(Res + i0);
                float2 r1 = *(const float2*)(Res + i1);
                o0.x += r0.x; o0.y += r0.y;
                o1.x += r1.x; o1.y += r1.y;
            }
            *(float2*)(C + i0) = o0;
            *(float2*)(C + i1) = o1;
        }
    }
}

// ---------------- rmsnorm: one block per row (writes fp32 + fp16) ----------------
__global__ void rmsnorm_kernel(const float* __restrict__ X, const float* __restrict__ W,
                               float* __restrict__ Y, __half* __restrict__ Yh, int D)
{
    const int m = blockIdx.x, tid = threadIdx.x;   // 256 threads
    const float* x = X + (size_t)m * D;
    float s = 0.f;
    for (int k = tid * 4; k < D; k += 1024) {
        float4 v = *(const float4*)(x + k);
        s += v.x * v.x + v.y * v.y + v.z * v.z + v.w * v.w;
    }
    __shared__ float red[9];
    #pragma unroll
    for (int off = 16; off > 0; off >>= 1) s += __shfl_xor_sync(0xffffffffu, s, off);
    if ((tid & 31) == 0) red[tid >> 5] = s;
    __syncthreads();
    if (tid == 0) {
        float t = 0.f;
        #pragma unroll
        for (int i = 0; i < 8; i++) t += red[i];
        red[8] = rsqrtf(t / (float)D + 1e-5f);
    }
    __syncthreads();
    const float inv = red[8];
    float* y = Y + (size_t)m * D;
    __half* yh = Yh + (size_t)m * D;
    for (int k = tid * 4; k < D; k += 1024) {
        float4 v = *(const float4*)(x + k);
        float4 w = *(const float4*)(W + k);
        v.x = v.x * inv * w.x;
        v.y = v.y * inv * w.y;
        v.z = v.z * inv * w.z;
        v.w = v.w * inv * w.w;
        *(float4*)(y + k) = v;
        uint2 hp = make_uint2(pack_h2(v.x, v.y), pack_h2(v.z, v.w));
        *(uint2*)(yh + k) = hp;
    }
}

// ---------------- LoRA down-projection: T[M,16] = LSCALE * X[M,K] @ A[16,K]^T ----------------
__global__ void lora_tmp_kernel(const float* __restrict__ X, const float* __restrict__ Aw,
                                float* __restrict__ T, int K)
{
    const int m = blockIdx.x;
    const int w = threadIdx.x >> 5, lane = threadIdx.x & 31;
    const float* x = X + (size_t)m * K;
    const float* a = Aw + (size_t)w * K;
    float s = 0.f;
    for (int k = lane * 4; k < K; k += 128) {
        float4 xv = *(const float4*)(x + k);
        float4 av = *(const float4*)(a + k);
        s += xv.x * av.x + xv.y * av.y + xv.z * av.z + xv.w * av.w;
    }
    #pragma unroll
    for (int off = 16; off > 0; off >>= 1) s += __shfl_xor_sync(0xffffffffu, s, off);
    if (lane == 0) T[m * RLORA + w] = s * LSCALE;
}

// ---------------- RoPE (interleaved pairs), in place ----------------
__global__ void rope_kernel(float* __restrict__ X, const float* __restrict__ Cc,
                            const float* __restrict__ Sn, int H, int total)
{
    const int idx = blockIdx.x * blockDim.x + threadIdx.x;
    if (idx >= total) return;
    const int i = idx & 63;
    const int rest = idx >> 6;
    const int h = rest % H;
    const int s = rest / H;
    const float c = Cc[s * 64 + i], sn = Sn[s * 64 + i];
    float* p = X + (size_t)s * (H * 128) + h * 128 + 2 * i;
    const float x1 = p[0], x2 = p[1];
    p[0] = x1 * c - x2 * sn;
    p[1] = x1 * sn + x2 * c;
}

// ---------------- flash attention fp32: 64x64 tiles, causal, GQA 4:1 ----------------
__global__ __launch_bounds__(256) void flash_kernel(
    const float* __restrict__ Q, const float* __restrict__ Kk,
    const float* __restrict__ V, float* __restrict__ O, __half* __restrict__ Oh)
{
    extern __shared__ float smf[];
    float* Qs = smf;
    float* Ks = smf + 128 * 64;
    float* Vs = smf + 2 * 128 * 64;
    float* Ps = smf + 3 * 128 * 64;

    const int qb = blockIdx.x, head = blockIdx.y;
    const int kvh = head >> 2;
    const int tid = threadIdx.x;
    const int ty = tid >> 4, tx = tid & 15;
    const int qr0 = qb * 64;

    const float* Qg = Q + (size_t)qr0 * DM + head * 128;
    for (int li = tid; li < 2048; li += 256) {
        const int r = li >> 5, c4 = li & 31;
        float4 v = *(const float4*)(Qg + (size_t)r * DM + c4 * 4);
        Qs[(c4 * 4 + 0) * 64 + r] = v.x;
        Qs[(c4 * 4 + 1) * 64 + r] = v.y;
        Qs[(c4 * 4 + 2) * 64 + r] = v.z;
        Qs[(c4 * 4 + 3) * 64 + r] = v.w;
    }

    float m_i[4], l_i[4], acc[4][8];
    #pragma unroll
    for (int i = 0; i < 4; i++) {
        m_i[i] = -1e30f; l_i[i] = 0.f;
        #pragma unroll
        for (int j = 0; j < 8; j++) acc[i][j] = 0.f;
    }
    const float scale = 0.088388347648318447f;

    for (int kb = 0; kb <= qb; kb++) {
        __syncthreads();
        const float* Kg = Kk + (size_t)(kb * 64) * KVDIM + kvh * 128;
        const float* Vg = V + (size_t)(kb * 64) * KVDIM + kvh * 128;
        for (int li = tid; li < 2048; li += 256) {
            const int r = li >> 5, c4 = li & 31;
            float4 kv = *(const float4*)(Kg + (size_t)r * KVDIM + c4 * 4);
            Ks[(c4 * 4 + 0) * 64 + r] = kv.x;
            Ks[(c4 * 4 + 1) * 64 + r] = kv.y;
            Ks[(c4 * 4 + 2) * 64 + r] = kv.z;
            Ks[(c4 * 4 + 3) * 64 + r] = kv.w;
            float4 vv = *(const float4*)(Vg + (size_t)r * KVDIM + c4 * 4);
            *(float4*)(Vs + r * 128 + c4 * 4) = vv;
        }
        __syncthreads();

        float sc[4][4];
        #pragma unroll
        for (int i = 0; i < 4; i++)
            #pragma unroll
            for (int j = 0; j < 4; j++) sc[i][j] = 0.f;
        for (int kk = 0; kk < 128; kk++) {
            float4 a = *(const float4*)(Qs + kk * 64 + ty * 4);
            float4 b = *(const float4*)(Ks + kk * 64 + tx * 4);
            const float av[4] = {a.x, a.y, a.z, a.w};
            const float bv[4] = {b.x, b.y, b.z, b.w};
            #pragma unroll
            for (int i = 0; i < 4; i++)
                #pragma unroll
                for (int j = 0; j < 4; j++)
                    sc[i][j] = fmaf(av[i], bv[j], sc[i][j]);
        }
        #pragma unroll
        for (int i = 0; i < 4; i++)
            #pragma unroll
            for (int j = 0; j < 4; j++) {
                sc[i][j] *= scale;
                if (kb == qb && (kb * 64 + tx * 4 + j) > (qr0 + ty * 4 + i))
                    sc[i][j] = -1e30f;
            }

        #pragma unroll
        for (int i = 0; i < 4; i++) {
            float mloc = fmaxf(fmaxf(sc[i][0], sc[i][1]), fmaxf(sc[i][2], sc[i][3]));
            #pragma unroll
            for (int off = 8; off > 0; off >>= 1)
                mloc = fmaxf(mloc, __shfl_xor_sync(0xffffffffu, mloc, off));
            const float mnew = fmaxf(m_i[i], mloc);
            const float al = __expf(m_i[i] - mnew);
            const float p0 = __expf(sc[i][0] - mnew);
            const float p1 = __expf(sc[i][1] - mnew);
            const float p2 = __expf(sc[i][2] - mnew);
            const float p3 = __expf(sc[i][3] - mnew);
            float rs = p0 + p1 + p2 + p3;
            #pragma unroll
            for (int off = 8; off > 0; off >>= 1)
                rs += __shfl_xor_sync(0xffffffffu, rs, off);
            m_i[i] = mnew;
            l_i[i] = l_i[i] * al + rs;
            #pragma unroll
            for (int j = 0; j < 8; j++) acc[i][j] *= al;
            float* pr = Ps + (ty * 4 + i) * 64 + tx * 4;
            pr[0] = p0; pr[1] = p1; pr[2] = p2; pr[3] = p3;
        }
        __syncthreads();

        #pragma unroll 4
        for (int j = 0; j < 64; j++) {
            const float a0 = Ps[(ty * 4 + 0) * 64 + j];
            const float a1 = Ps[(ty * 4 + 1) * 64 + j];
            const float a2 = Ps[(ty * 4 + 2) * 64 + j];
            const float a3 = Ps[(ty * 4 + 3) * 64 + j];
            float4 b0 = *(const float4*)(Vs + j * 128 + tx * 8);
            float4 b1 = *(const float4*)(Vs + j * 128 + tx * 8 + 4);
            const float bv[8] = {b0.x, b0.y, b0.z, b0.w, b1.x, b1.y, b1.z, b1.w};
            #pragma unroll
            for (int jj = 0; jj < 8; jj++) {
                acc[0][jj] = fmaf(a0, bv[jj], acc[0][jj]);
                acc[1][jj] = fmaf(a1, bv[jj], acc[1][jj]);
                acc[2][jj] = fmaf(a2, bv[jj], acc[2][jj]);
                acc[3][jj] = fmaf(a3, bv[jj], acc[3][jj]);
            }
        }
    }

    #pragma unroll
    for (int i = 0; i < 4; i++) {
        const float inv = 1.f / l_i[i];
        const int gr = qr0 + ty * 4 + i;
        const size_t base = (size_t)gr * DM + head * 128 + tx * 8;
        float o[8];
        #pragma unroll
        for (int j = 0; j < 8; j++) o[j] = acc[i][j] * inv;
        *(float4*)(O + base)     = make_float4(o[0], o[1], o[2], o[3]);
        *(float4*)(O + base + 4) = make_float4(o[4], o[5], o[6], o[7]);
        uint4 hp = make_uint4(pack_h2(o[0], o[1]), pack_h2(o[2], o[3]),
                              pack_h2(o[4], o[5]), pack_h2(o[6], o[7]));
        *(uint4*)(Oh + base) = hp;
    }
}

// ---------------- SwiGLU: G = silu(G) * U (fp32 in place + fp16 mirror) ----------------
__global__ void silu_mul_kernel(float* __restrict__ G, const float* __restrict__ U,
                                __half* __restrict__ Gh, int n4)
{
    const int i = blockIdx.x * blockDim.x + threadIdx.x;
    if (i >= n4) return;
    float4 g = ((const float4*)G)[i];
    float4 u = ((const float4*)U)[i];
    g.x = g.x / (1.f + __expf(-g.x)) * u.x;
    g.y = g.y / (1.f + __expf(-g.y)) * u.y;
    g.z = g.z / (1.f + __expf(-g.z)) * u.z;
    g.w = g.w / (1.f + __expf(-g.w)) * u.w;
    ((float4*)G)[i] = g;
    uint2 hp = make_uint2(pack_h2(g.x, g.y), pack_h2(g.z, g.w));
    ((uint2*)Gh)[i] = hp;
}

// ---------------- launcher ----------------
#define GEMM_SMEM 65536

extern "C" void kernel_launch(void* const* d_in, const int* in_sizes, int n_in,
                              void* d_out, int out_size)
{
    const float* data      = (const float*)d_in[0];
    const float* cosp      = (const float*)d_in[2];
    const float* sinp      = (const float*)d_in[3];
    const float* attn_norm = (const float*)d_in[4];
    const float* wq        = (const float*)d_in[5];
    const float* wk        = (const float*)d_in[6];
    const float* wv        = (const float*)d_in[7];
    const float* wo        = (const float*)d_in[8];
    const float* wq_a      = (const float*)d_in[9];
    const float* wq_b      = (const float*)d_in[10];
    const float* wk_a      = (const float*)d_in[11];
    const float* wk_b      = (const float*)d_in[12];
    const float* wv_a      = (const float*)d_in[13];
    const float* wv_b      = (const float*)d_in[14];
    const float* wo_a      = (const float*)d_in[15];
    const float* wo_b      = (const float*)d_in[16];
    const float* ffn_norm  = (const float*)d_in[17];
    const float* w1        = (const float*)d_in[18];
    const float* w2        = (const float*)d_in[19];
    const float* w3        = (const float*)d_in[20];
    const float* w1_a      = (const float*)d_in[21];
    const float* w1_b      = (const float*)d_in[22];
    const float* w2_a      = (const float*)d_in[23];
    const float* w2_b      = (const float*)d_in[24];
    const float* w3_a      = (const float*)d_in[25];
    const float* w3_b      = (const float*)d_in[26];
    float* out = (float*)d_out;

    float *h, *q, *k, *v, *attn, *res2, *gate, *up, *tmp;
    cudaGetSymbolAddress((void**)&h, g_h);
    cudaGetSymbolAddress((void**)&q, g_q);
    cudaGetSymbolAddress((void**)&k, g_k);
    cudaGetSymbolAddress((void**)&v, g_v);
    cudaGetSymbolAddress((void**)&attn, g_attn);
    cudaGetSymbolAddress((void**)&res2, g_res2);
    cudaGetSymbolAddress((void**)&gate, g_gate);
    cudaGetSymbolAddress((void**)&up, g_up);
    cudaGetSymbolAddress((void**)&tmp, g_tmp);

    __half *wq_h, *wk_h, *wv_h, *wo_h, *w1_h, *w3_h, *w2_h, *h_h, *attn_h, *gu_h;
    cudaGetSymbolAddress((void**)&wq_h, g_wq_h);
    cudaGetSymbolAddress((void**)&wk_h, g_wk_h);
    cudaGetSymbolAddress((void**)&wv_h, g_wv_h);
    cudaGetSymbolAddress((void**)&wo_h, g_wo_h);
    cudaGetSymbolAddress((void**)&w1_h, g_w1_h);
    cudaGetSymbolAddress((void**)&w3_h, g_w3_h);
    cudaGetSymbolAddress((void**)&w2_h, g_w2_h);
    cudaGetSymbolAddress((void**)&h_h, g_h_h);
    cudaGetSymbolAddress((void**)&attn_h, g_attn_h);
    cudaGetSymbolAddress((void**)&gu_h, g_gu_h);

    cudaFuncSetAttribute(flash_kernel, cudaFuncAttributeMaxDynamicSharedMemorySize, 114688);
    cudaFuncSetAttribute(gemm_fp16, cudaFuncAttributeMaxDynamicSharedMemorySize, GEMM_SMEM);

    // ---- weight conversions (fp32 -> fp16) ----
    f2h_kernel<<<(DM * DM / 4) / 256, 256>>>(wq, wq_h, DM * DM / 4);
    f2h_kernel<<<(KVDIM * DM / 4) / 256, 256>>>(wk, wk_h, KVDIM * DM / 4);
    f2h_kernel<<<(KVDIM * DM / 4) / 256, 256>>>(wv, wv_h, KVDIM * DM / 4);
    f2h_kernel<<<(DM * DM / 4) / 256, 256>>>(wo, wo_h, DM * DM / 4);
    f2h_kernel<<<(FF * DM / 4) / 256, 256>>>(w1, w1_h, FF * DM / 4);
    f2h_kernel<<<(FF * DM / 4) / 256, 256>>>(w3, w3_h, FF * DM / 4);
    f2h_kernel<<<(DM * FF / 4) / 256, 256>>>(w2, w2_h, DM * FF / 4);

    // ---- attention block ----
    rmsnorm_kernel<<<SLEN, 256>>>(data, attn_norm, h, h_h, DM);

    lora_tmp_kernel<<<SLEN, 512>>>(h, wq_a, tmp, DM);
    gemm_fp16<<<dim3(SLEN / 128, DM / 128), 256, GEMM_SMEM>>>(h_h, wq_h, tmp, wq_b, nullptr, q, SLEN, DM, DM);
    rope_kernel<<<(SLEN * 32 * 64) / 256, 256>>>(q, cosp, sinp, 32, SLEN * 32 * 64);

    lora_tmp_kernel<<<SLEN, 512>>>(h, wk_a, tmp, DM);
    gemm_fp16<<<dim3(SLEN / 128, KVDIM / 128), 256, GEMM_SMEM>>>(h_h, wk_h, tmp, wk_b, nullptr, k, SLEN, KVDIM, DM);
    rope_kernel<<<(SLEN * 8 * 64) / 256, 256>>>(k, cosp, sinp, 8, SLEN * 8 * 64);

    lora_tmp_kernel<<<SLEN, 512>>>(h, wv_a, tmp, DM);
    gemm_fp16<<<dim3(SLEN / 128, KVDIM / 128), 256, GEMM_SMEM>>>(h_h, wv_h, tmp, wv_b, nullptr, v, SLEN, KVDIM, DM);

    flash_kernel<<<dim3(SLEN / 64, 32), 256, 114688>>>(q, k, v, attn, attn_h);

    lora_tmp_kernel<<<SLEN, 512>>>(attn, wo_a, tmp, DM);
    gemm_fp16<<<dim3(SLEN / 128, DM / 128), 256, GEMM_SMEM>>>(attn_h, wo_h, tmp, wo_b, data, res2, SLEN, DM, DM);

    // ---- FFN block ----
    rmsnorm_kernel<<<SLEN, 256>>>(res2, ffn_norm, h, h_h, DM);

    lora_tmp_kernel<<<SLEN, 512>>>(h, w1_a, tmp, DM);
    gemm_fp16<<<dim3(SLEN / 128, FF / 128), 256, GEMM_SMEM>>>(h_h, w1_h, tmp, w1_b, nullptr, gate, SLEN, FF, DM);

    lora_tmp_kernel<<<SLEN, 512>>>(h, w3_a, tmp, DM);
    gemm_fp16<<<dim3(SLEN / 128, FF / 128), 256, GEMM_SMEM>>>(h_h, w3_h, tmp, w3_b, nullptr, up, SLEN, FF, DM);

    silu_mul_kernel<<<(SLEN * FF / 4) / 256, 256>>>(gate, up, gu_h, SLEN * FF / 4);

    lora_tmp_kernel<<<SLEN, 512>>>(gate, w2_a, tmp, FF);
    gemm_fp16<<<dim3(SLEN / 128, DM / 128), 256, GEMM_SMEM>>>(gu_h, w2_h, tmp, w2_b, res2, out, SLEN, DM, FF);
}